// round 1
// baseline (speedup 1.0000x reference)
#include <cuda_runtime.h>
#include <cuda_bf16.h>
#include <math.h>

// Problem dims (fixed by the dataset)
#define BATCH 1024
#define SEQ   512
#define DIM   768

// Scratch (allocation-free rule: __device__ globals)
__device__ float g_pooled[BATCH * DIM];
__device__ float g_hidden[BATCH * DIM];

// ---------------------------------------------------------------------------
// Kernel 1: masked sum pooling over sequence dim.
// One block per batch element. Compact active sequence indices into shared
// memory (whole-row skip when mask==0 -> halves DRAM traffic), then each of
// 384 threads accumulates one float2 (768 floats = 384 float2) over the
// active rows, unrolled x4 for MLP.
// ---------------------------------------------------------------------------
__global__ __launch_bounds__(384) void pool_kernel(
    const float* __restrict__ x,      // [BATCH, SEQ, DIM]
    const int*   __restrict__ mask)   // [BATCH, SEQ] (bool -> int32)
{
    __shared__ int s_idx[SEQ];
    __shared__ int s_cnt;

    const int b   = blockIdx.x;
    const int tid = threadIdx.x;  // 0..383

    if (tid == 0) s_cnt = 0;
    __syncthreads();

    // Compact active row indices (order irrelevant for a sum).
    const int* mrow = mask + (size_t)b * SEQ;
    for (int s = tid; s < SEQ; s += 384) {
        if (mrow[s] != 0) {
            int p = atomicAdd(&s_cnt, 1);
            s_idx[p] = s;
        }
    }
    __syncthreads();

    const int cnt = s_cnt;
    const float2* base = reinterpret_cast<const float2*>(x + (size_t)b * SEQ * DIM);
    // row stride in float2 units
    const int rs2 = DIM / 2;  // 384

    float2 acc;
    acc.x = 0.f; acc.y = 0.f;

    int i = 0;
    for (; i + 4 <= cnt; i += 4) {
        int s0 = s_idx[i + 0];
        int s1 = s_idx[i + 1];
        int s2 = s_idx[i + 2];
        int s3 = s_idx[i + 3];
        float2 v0 = base[(size_t)s0 * rs2 + tid];
        float2 v1 = base[(size_t)s1 * rs2 + tid];
        float2 v2 = base[(size_t)s2 * rs2 + tid];
        float2 v3 = base[(size_t)s3 * rs2 + tid];
        acc.x += (v0.x + v1.x) + (v2.x + v3.x);
        acc.y += (v0.y + v1.y) + (v2.y + v3.y);
    }
    for (; i < cnt; i++) {
        float2 v = base[(size_t)s_idx[i] * rs2 + tid];
        acc.x += v.x;
        acc.y += v.y;
    }

    reinterpret_cast<float2*>(g_pooled + (size_t)b * DIM)[tid] = acc;
}

// ---------------------------------------------------------------------------
// Kernel 2: C = tanh(A @ B + bias)
// A: [M, K] row-major, B: [K, N] row-major, C: [M, N]
// Tile: BM=64, BN=64, BK=16; 128 threads; per-thread microtile 8x4.
// Dims are multiples of tile sizes (M=1024, N=768, K=768) -> no bounds checks.
// ---------------------------------------------------------------------------
#define BM 64
#define BN 64
#define BK 16
#define TM 8
#define TN 4

__global__ __launch_bounds__(128) void gemm_bias_tanh(
    const float* __restrict__ A,
    const float* __restrict__ Bm,
    const float* __restrict__ bias,
    float* __restrict__ C,
    int M, int N, int K)
{
    __shared__ float As[BK][BM];   // transposed A tile: As[k][m]
    __shared__ float Bs[BK][BN];   // Bs[k][n]

    const int tid = threadIdx.x;      // 0..127
    const int tx  = tid % 16;         // col group: 16 * TN(4) = 64
    const int ty  = tid / 16;         // row group: 8  * TM(8) = 64

    const int m0 = blockIdx.y * BM;
    const int n0 = blockIdx.x * BN;

    float acc[TM][TN];
#pragma unroll
    for (int i = 0; i < TM; i++)
#pragma unroll
        for (int j = 0; j < TN; j++)
            acc[i][j] = 0.f;

    for (int k0 = 0; k0 < K; k0 += BK) {
        // --- load A tile: 64x16 floats = 256 float4, 2 per thread ---
#pragma unroll
        for (int l = 0; l < 2; l++) {
            int id = tid + l * 128;      // 0..255
            int ar = id >> 2;            // 0..63
            int ac = (id & 3) << 2;      // 0,4,8,12
            float4 v = *reinterpret_cast<const float4*>(
                A + (size_t)(m0 + ar) * K + k0 + ac);
            As[ac + 0][ar] = v.x;
            As[ac + 1][ar] = v.y;
            As[ac + 2][ar] = v.z;
            As[ac + 3][ar] = v.w;
        }
        // --- load B tile: 16x64 floats = 256 float4, 2 per thread ---
#pragma unroll
        for (int l = 0; l < 2; l++) {
            int id = tid + l * 128;      // 0..255
            int br = id >> 4;            // 0..15
            int bc = (id & 15) << 2;     // 0..60
            float4 v = *reinterpret_cast<const float4*>(
                Bm + (size_t)(k0 + br) * N + n0 + bc);
            *reinterpret_cast<float4*>(&Bs[br][bc]) = v;
        }
        __syncthreads();

#pragma unroll
        for (int kk = 0; kk < BK; kk++) {
            float a[TM];
            float bfrag[TN];
            float4 a0 = *reinterpret_cast<const float4*>(&As[kk][ty * TM + 0]);
            float4 a1 = *reinterpret_cast<const float4*>(&As[kk][ty * TM + 4]);
            a[0] = a0.x; a[1] = a0.y; a[2] = a0.z; a[3] = a0.w;
            a[4] = a1.x; a[5] = a1.y; a[6] = a1.z; a[7] = a1.w;
            float4 b0 = *reinterpret_cast<const float4*>(&Bs[kk][tx * TN]);
            bfrag[0] = b0.x; bfrag[1] = b0.y; bfrag[2] = b0.z; bfrag[3] = b0.w;
#pragma unroll
            for (int i = 0; i < TM; i++)
#pragma unroll
                for (int j = 0; j < TN; j++)
                    acc[i][j] = fmaf(a[i], bfrag[j], acc[i][j]);
        }
        __syncthreads();
    }

    // Epilogue: bias + tanh, vectorized float4 store.
    const int col = n0 + tx * TN;
    float4 bv = *reinterpret_cast<const float4*>(bias + col);
#pragma unroll
    for (int i = 0; i < TM; i++) {
        int row = m0 + ty * TM + i;
        float4 o;
        o.x = tanhf(acc[i][0] + bv.x);
        o.y = tanhf(acc[i][1] + bv.y);
        o.z = tanhf(acc[i][2] + bv.z);
        o.w = tanhf(acc[i][3] + bv.w);
        *reinterpret_cast<float4*>(C + (size_t)row * N + col) = o;
    }
}

// ---------------------------------------------------------------------------
// Launch
// ---------------------------------------------------------------------------
extern "C" void kernel_launch(void* const* d_in, const int* in_sizes, int n_in,
                              void* d_out, int out_size)
{
    const float* token_embeds = (const float*)d_in[0];
    const int*   attn_mask    = (const int*)  d_in[1];
    const float* W1           = (const float*)d_in[2];
    const float* b1           = (const float*)d_in[3];
    const float* W2           = (const float*)d_in[4];
    const float* b2           = (const float*)d_in[5];
    float*       out          = (float*)d_out;

    float* pooled = nullptr;
    float* hidden = nullptr;
    cudaGetSymbolAddress((void**)&pooled, g_pooled);
    cudaGetSymbolAddress((void**)&hidden, g_hidden);

    // 1) masked sum pooling
    pool_kernel<<<BATCH, 384>>>(token_embeds, attn_mask);

    // 2) h = tanh(pooled @ W1 + b1)
    dim3 grid1(DIM / BN, BATCH / BM);   // (12, 16)
    gemm_bias_tanh<<<grid1, 128>>>(pooled, W1, b1, hidden, BATCH, DIM, DIM);

    // 3) out = tanh(h @ W2 + b2)
    gemm_bias_tanh<<<grid1, 128>>>(hidden, W2, b2, out, BATCH, DIM, DIM);
}

// round 2
// speedup vs baseline: 1.1003x; 1.1003x over previous
#include <cuda_runtime.h>
#include <cuda_bf16.h>
#include <math.h>
#include <stdint.h>

// Problem dims (fixed by the dataset)
#define BATCH 1024
#define SEQ   512
#define DIM   768

// Scratch (allocation-free rule: __device__ globals)
__device__ float g_pooled[BATCH * DIM];
__device__ float g_hidden[BATCH * DIM];

// ---------------------------------------------------------------------------
// Kernel 1: masked sum pooling (unchanged from R1: 83% DRAM, near roofline)
// ---------------------------------------------------------------------------
__global__ __launch_bounds__(384) void pool_kernel(
    const float* __restrict__ x,      // [BATCH, SEQ, DIM]
    const int*   __restrict__ mask)   // [BATCH, SEQ]
{
    __shared__ int s_idx[SEQ];
    __shared__ int s_cnt;

    const int b   = blockIdx.x;
    const int tid = threadIdx.x;

    if (tid == 0) s_cnt = 0;
    __syncthreads();

    const int* mrow = mask + (size_t)b * SEQ;
    for (int s = tid; s < SEQ; s += 384) {
        if (mrow[s] != 0) {
            int p = atomicAdd(&s_cnt, 1);
            s_idx[p] = s;
        }
    }
    __syncthreads();

    const int cnt = s_cnt;
    const float2* base = reinterpret_cast<const float2*>(x + (size_t)b * SEQ * DIM);
    const int rs2 = DIM / 2;

    float2 acc; acc.x = 0.f; acc.y = 0.f;

    int i = 0;
    for (; i + 4 <= cnt; i += 4) {
        int s0 = s_idx[i + 0];
        int s1 = s_idx[i + 1];
        int s2 = s_idx[i + 2];
        int s3 = s_idx[i + 3];
        float2 v0 = base[(size_t)s0 * rs2 + tid];
        float2 v1 = base[(size_t)s1 * rs2 + tid];
        float2 v2 = base[(size_t)s2 * rs2 + tid];
        float2 v3 = base[(size_t)s3 * rs2 + tid];
        acc.x += (v0.x + v1.x) + (v2.x + v3.x);
        acc.y += (v0.y + v1.y) + (v2.y + v3.y);
    }
    for (; i < cnt; i++) {
        float2 v = base[(size_t)s_idx[i] * rs2 + tid];
        acc.x += v.x;
        acc.y += v.y;
    }

    reinterpret_cast<float2*>(g_pooled + (size_t)b * DIM)[tid] = acc;
}

// ---------------------------------------------------------------------------
// Kernel 2: C = tanh(A @ B + bias), error-compensated TF32 tensor-core GEMM.
// A[M,K] row-major, B[K,N] row-major, C[M,N].
// x = hi + lo split (hi: top 13 mantissa bits, lo: exact residual), accumulate
// Ahi*Bhi + Ahi*Blo + Alo*Bhi -> fp32-grade accuracy, 3x MMA (cheap on tensor).
// Tiles: BM=BN=64, BK=32; 128 threads = 4 warps (2x2), warp tile 32x32 built
// from m16n8k8 mma (2 M-tiles x 4 N-tiles).
// ---------------------------------------------------------------------------
#define BM 64
#define BN 64
#define BK 32
#define ASL 66   // As row stride (k-major, padded)
#define BSL 68   // Bs row stride (k-major, padded; 16B-aligned rows for STS.128)

__device__ __forceinline__ void split_tf32(float x, uint32_t& hi, uint32_t& lo)
{
    uint32_t xb = __float_as_uint(x);
    hi = xb & 0xFFFFE000u;                         // truncate to tf32 mantissa
    lo = __float_as_uint(x - __uint_as_float(hi)); // exact residual
}

__device__ __forceinline__ void mma_tf32(
    float c[4], uint32_t a0, uint32_t a1, uint32_t a2, uint32_t a3,
    uint32_t b0, uint32_t b1)
{
    asm volatile(
        "mma.sync.aligned.m16n8k8.row.col.f32.tf32.tf32.f32 "
        "{%0,%1,%2,%3}, {%4,%5,%6,%7}, {%8,%9}, {%0,%1,%2,%3};\n"
        : "+f"(c[0]), "+f"(c[1]), "+f"(c[2]), "+f"(c[3])
        : "r"(a0), "r"(a1), "r"(a2), "r"(a3), "r"(b0), "r"(b1));
}

__global__ __launch_bounds__(128) void gemm_tf32_bias_tanh(
    const float* __restrict__ A,
    const float* __restrict__ Bm,
    const float* __restrict__ bias,
    float* __restrict__ C,
    int M, int N, int K)
{
    __shared__ float As[BK][ASL];   // As[k][m]
    __shared__ float Bs[BK][BSL];   // Bs[k][n]

    const int tid  = threadIdx.x;
    const int lane = tid & 31;
    const int warp = tid >> 5;       // 0..3
    const int gid  = lane >> 2;      // 0..7
    const int tig  = lane & 3;       // 0..3
    const int warpM = (warp & 1) * 32;
    const int warpN = (warp >> 1) * 32;

    const int m0 = blockIdx.y * BM;
    const int n0 = blockIdx.x * BN;

    float acc[2][4][4];
#pragma unroll
    for (int mt = 0; mt < 2; mt++)
#pragma unroll
        for (int nt = 0; nt < 4; nt++)
#pragma unroll
            for (int r = 0; r < 4; r++)
                acc[mt][nt][r] = 0.f;

    for (int k0 = 0; k0 < K; k0 += BK) {
        // --- A tile: 64x32, transpose into As[k][m]. 512 float4, 4/thread ---
#pragma unroll
        for (int l = 0; l < 4; l++) {
            int id = tid + l * 128;          // 0..511
            int ar = id >> 3;                // 0..63
            int ac = (id & 7) << 2;          // 0..28
            float4 v = *reinterpret_cast<const float4*>(
                A + (size_t)(m0 + ar) * K + k0 + ac);
            As[ac + 0][ar] = v.x;
            As[ac + 1][ar] = v.y;
            As[ac + 2][ar] = v.z;
            As[ac + 3][ar] = v.w;
        }
        // --- B tile: 32x64, direct float4 into Bs[k][n]. 512 f4, 4/thread ---
#pragma unroll
        for (int l = 0; l < 4; l++) {
            int id = tid + l * 128;
            int br = id >> 4;                // 0..31
            int bc = (id & 15) << 2;         // 0..60
            *reinterpret_cast<float4*>(&Bs[br][bc]) =
                *reinterpret_cast<const float4*>(
                    Bm + (size_t)(k0 + br) * N + n0 + bc);
        }
        __syncthreads();

#pragma unroll
        for (int ks = 0; ks < 4; ks++) {
            const int kb = ks * 8;

            uint32_t ah[2][4], al[2][4];
#pragma unroll
            for (int mt = 0; mt < 2; mt++) {
                int rm = warpM + mt * 16 + gid;
                split_tf32(As[kb + tig    ][rm    ], ah[mt][0], al[mt][0]);
                split_tf32(As[kb + tig    ][rm + 8], ah[mt][1], al[mt][1]);
                split_tf32(As[kb + tig + 4][rm    ], ah[mt][2], al[mt][2]);
                split_tf32(As[kb + tig + 4][rm + 8], ah[mt][3], al[mt][3]);
            }
            uint32_t bh[4][2], bl[4][2];
#pragma unroll
            for (int nt = 0; nt < 4; nt++) {
                int nn = warpN + nt * 8 + gid;
                split_tf32(Bs[kb + tig    ][nn], bh[nt][0], bl[nt][0]);
                split_tf32(Bs[kb + tig + 4][nn], bh[nt][1], bl[nt][1]);
            }

#pragma unroll
            for (int mt = 0; mt < 2; mt++)
#pragma unroll
                for (int nt = 0; nt < 4; nt++) {
                    mma_tf32(acc[mt][nt], ah[mt][0], ah[mt][1], ah[mt][2], ah[mt][3],
                             bh[nt][0], bh[nt][1]);
                    mma_tf32(acc[mt][nt], ah[mt][0], ah[mt][1], ah[mt][2], ah[mt][3],
                             bl[nt][0], bl[nt][1]);
                    mma_tf32(acc[mt][nt], al[mt][0], al[mt][1], al[mt][2], al[mt][3],
                             bh[nt][0], bh[nt][1]);
                }
        }
        __syncthreads();
    }

    // Epilogue: bias + tanh. c0/c1 are adjacent cols; c2/c3 row+8.
#pragma unroll
    for (int mt = 0; mt < 2; mt++) {
#pragma unroll
        for (int nt = 0; nt < 4; nt++) {
            int row = m0 + warpM + mt * 16 + gid;
            int col = n0 + warpN + nt * 8 + tig * 2;
            float2 bv = *reinterpret_cast<const float2*>(bias + col);
            float2 o0;
            o0.x = tanhf(acc[mt][nt][0] + bv.x);
            o0.y = tanhf(acc[mt][nt][1] + bv.y);
            *reinterpret_cast<float2*>(C + (size_t)row * N + col) = o0;
            float2 o1;
            o1.x = tanhf(acc[mt][nt][2] + bv.x);
            o1.y = tanhf(acc[mt][nt][3] + bv.y);
            *reinterpret_cast<float2*>(C + (size_t)(row + 8) * N + col) = o1;
        }
    }
}

// ---------------------------------------------------------------------------
// Launch
// ---------------------------------------------------------------------------
extern "C" void kernel_launch(void* const* d_in, const int* in_sizes, int n_in,
                              void* d_out, int out_size)
{
    const float* token_embeds = (const float*)d_in[0];
    const int*   attn_mask    = (const int*)  d_in[1];
    const float* W1           = (const float*)d_in[2];
    const float* b1           = (const float*)d_in[3];
    const float* W2           = (const float*)d_in[4];
    const float* b2           = (const float*)d_in[5];
    float*       out          = (float*)d_out;

    float* pooled = nullptr;
    float* hidden = nullptr;
    cudaGetSymbolAddress((void**)&pooled, g_pooled);
    cudaGetSymbolAddress((void**)&hidden, g_hidden);

    // 1) masked sum pooling
    pool_kernel<<<BATCH, 384>>>(token_embeds, attn_mask);

    // 2) h = tanh(pooled @ W1 + b1)
    dim3 grid1(DIM / BN, BATCH / BM);   // (12, 16) = 192 blocks
    gemm_tf32_bias_tanh<<<grid1, 128>>>(pooled, W1, b1, hidden, BATCH, DIM, DIM);

    // 3) out = tanh(h @ W2 + b2)
    gemm_tf32_bias_tanh<<<grid1, 128>>>(hidden, W2, b2, out, BATCH, DIM, DIM);
}